// round 2
// baseline (speedup 1.0000x reference)
#include <cuda_runtime.h>

#define L_LEN   4096
#define DRAD    32                  // minimum_extrema_distance (fixed for this problem)
#define NTHR    256
#define PER     (L_LEN / NTHR)      // 16 positions per thread
#define LFULL   (L_LEN + 2 * DRAD)  // padded length 4160
#define NCHUNK  (LFULL / DRAD)      // 130 chunks of 32

__device__ __forceinline__ unsigned long long umax64(unsigned long long a, unsigned long long b) {
    return a > b ? a : b;
}

__global__ void __launch_bounds__(NTHR, 1)
extrema_nms_kernel(const float* __restrict__ x, float* __restrict__ out)
{
    // static shared: ~38.5 KB total
    __shared__ unsigned long long Af[LFULL];     // active keys, 0 = decided/non-extremum
    __shared__ unsigned long long M[NCHUNK];     // per-chunk max of Af
    __shared__ int cnt;                          // number of alive chunks
    __shared__ unsigned char dirty[NCHUNK];
    __shared__ unsigned char aliveC[NCHUNK];

    const int tid  = threadIdx.x;
    const int lane = tid & 31;
    const float* xr = x + (size_t)blockIdx.x * L_LEN;

    if (tid == 0) cnt = NCHUNK;
    if (tid < NCHUNK) { dirty[tid] = 1; aliveC[tid] = 1; }
    if (tid < 2 * DRAD) {                        // zero pads
        int idx = (tid < DRAD) ? tid : (L_LEN + DRAD + (tid - DRAD));
        Af[idx] = 0ull;
    }

    // Build keys. key = (fbits(|x|) << 13) | (L - p): descending |x|, ties -> lower p.
    // Unique and nonzero for every extremum; 0 otherwise. Matches reference stable argsort order.
    float xv[PER];
    #pragma unroll
    for (int k = 0; k < PER; k++) {
        int p = tid + k * NTHR;
        float xi = xr[p];
        xv[k] = xi;
        // reference pad semantics
        bool dxr = (p < L_LEN - 1) ? (xr[p + 1] > xi) : false;   // dx padded right with 0
        bool dxl = (p > 0)         ? (xi <= xr[p - 1]) : true;   // dx padded left with 0
        bool ispos = (xi > 0.0f);                                // neg = !(x > 0)
        bool isext = (dxr && dxl && !ispos) || (!dxr && !dxl && ispos);
        unsigned long long key = 0ull;
        if (isext) {
            unsigned int fb = __float_as_uint(fabsf(xi));
            key = (((unsigned long long)fb) << 13) | (unsigned long long)(L_LEN - p);
        }
        Af[DRAD + p] = key;
    }

    // Fixed point of: keep every undecided strict window-max; kept suppress +-DRAD.
    // Equals the sequential greedy exactly (keys are a total order).
    unsigned int keepAll = 0;
    int safety = 0;
    for (;;) {
        __syncthreads();   // (1) Af / dirty stable

        // Phase A: recompute chunk max for dirty chunks (thread per chunk, lane-rotated -> conflict-free)
        if (tid < NCHUNK && dirty[tid]) {
            int base = tid * DRAD;
            int rot = lane;
            unsigned long long m0 = 0, m1 = 0, m2 = 0, m3 = 0;
            #pragma unroll
            for (int i = 0; i < DRAD; i += 4) {
                m0 = umax64(m0, Af[base + ((i + 0 + rot) & 31)]);
                m1 = umax64(m1, Af[base + ((i + 1 + rot) & 31)]);
                m2 = umax64(m2, Af[base + ((i + 2 + rot) & 31)]);
                m3 = umax64(m3, Af[base + ((i + 3 + rot) & 31)]);
            }
            unsigned long long m = umax64(umax64(m0, m1), umax64(m2, m3));
            M[tid] = m;
            dirty[tid] = 0;
            unsigned char na = (m != 0ull);
            if (aliveC[tid] && !na) atomicSub(&cnt, 1);
            aliveC[tid] = na;
        }
        __syncthreads();   // (2) M / cnt ready

        if (cnt == 0 || ++safety > 256) break;

        // Phase B: decide. Only a chunk's max can be a window max (unique keys).
        // Window [fp-32, fp+32] spans exactly chunks c2-1, c2, c2+1 (partial, full, partial).
        unsigned int keptmask = 0;
        #pragma unroll
        for (int k = 0; k < PER; k++) {
            int fp = tid + k * NTHR + DRAD;
            int c2 = fp >> 5;
            unsigned long long m = M[c2];
            if (!m) continue;
            unsigned long long a = Af[fp];
            if (a != m) continue;                // not the chunk max -> cannot be window max
            bool ok = true;
            if (M[c2 - 1] > a) {                 // boundary check against left partial range
                int base = c2 << 5;
                unsigned long long wl = 0;
                for (int q = fp - DRAD; q < base; q++) wl = umax64(wl, Af[q]);
                ok = (a >= wl);
            }
            if (ok && M[c2 + 1] > a) {           // right partial range
                int base2 = (c2 + 1) << 5;
                unsigned long long wr = 0;
                for (int q = base2; q <= fp + DRAD; q++) wr = umax64(wr, Af[q]);
                ok = (a >= wr);
            }
            if (ok) keptmask |= (1u << k);
        }
        keepAll |= keptmask;
        __syncthreads();   // (3) all decide reads done before Af mutation

        // Phase C: suppression. Keepers are pairwise > DRAD apart; zero windows, mark dirty.
        unsigned int km = keptmask;
        while (km) {
            int k = __ffs(km) - 1;
            km &= km - 1;
            int fp = tid + k * NTHR + DRAD;
            #pragma unroll 1
            for (int q = fp - DRAD; q <= fp + DRAD; q++) Af[q] = 0ull;
            int c2 = fp >> 5;
            dirty[c2 - 1] = 1; dirty[c2] = 1; dirty[c2 + 1] = 1;
        }
    }

    // Output: kept extrema keep their value, everything else 0.
    float* orow = out + (size_t)blockIdx.x * L_LEN;
    #pragma unroll
    for (int k = 0; k < PER; k++) {
        int p = tid + k * NTHR;
        orow[p] = ((keepAll >> k) & 1u) ? xv[k] : 0.0f;
    }
}

extern "C" void kernel_launch(void* const* d_in, const int* in_sizes, int n_in,
                              void* d_out, int out_size)
{
    const float* x = (const float*)d_in[0];
    float* out = (float*)d_out;
    // d_in[1] is minimum_extrema_distance = 32 (compile-time constant DRAD)

    int nrows = out_size / L_LEN;   // 128
    extrema_nms_kernel<<<nrows, NTHR>>>(x, out);
}

// round 3
// speedup vs baseline: 1.1220x; 1.1220x over previous
#include <cuda_runtime.h>

#define L_LEN   4096
#define DRAD    32                 // minimum_extrema_distance (fixed for this problem)
#define NTHR    256
#define PER     (L_LEN / NTHR)     // 16
#define NCH     (L_LEN / 32)       // 128 chunks of 32
#define STL     8                  // sparse-table levels over chunks (1..128)
#define WCAP    192                // worklist capacity (alive intervals <= ~130)

typedef unsigned long long u64;
typedef unsigned int u32;

__device__ __forceinline__ u64 umax64(u64 a, u64 b) { return a > b ? a : b; }

__global__ void __launch_bounds__(NTHR, 1)
extrema_nms_kernel(const float* __restrict__ x, float* __restrict__ out)
{
    __shared__ u64 Af[L_LEN];            // static keys (0 = non-extremum)
    __shared__ u64 ST[STL][NCH];         // sparse table over 32-chunk maxima
    __shared__ unsigned char keep[L_LEN];
    __shared__ u32 listA[WCAP], listB[WCAP];
    __shared__ int nA, nB;

    const int tid  = threadIdx.x;
    const int lane = tid & 31;
    const float* xr = x + (size_t)blockIdx.x * L_LEN;

    // ---- keys: key = (fbits(|x|) << 13) | (L - p)  (desc |x|, ties -> lower p; unique, nonzero iff extremum)
    float xv[PER];
    #pragma unroll
    for (int k = 0; k < PER; k++) {
        int p = tid + k * NTHR;
        float xi = xr[p];
        xv[k] = xi;
        keep[p] = 0;
        // reference pad semantics: dx padded right with 0 (>0 false), left with 0 (<=0 true)
        bool dxr = (p < L_LEN - 1) ? (xr[p + 1] > xi) : false;
        bool dxl = (p > 0)         ? (xi <= xr[p - 1]) : true;
        bool ispos = (xi > 0.0f);
        bool isext = (dxr && dxl && !ispos) || (!dxr && !dxl && ispos);
        u64 key = 0ull;
        if (isext) {
            u32 fb = __float_as_uint(fabsf(xi));
            key = (((u64)fb) << 13) | (u64)(L_LEN - p);
        }
        Af[p] = key;
    }
    if (tid == 0) { nA = 1; nB = 0; listA[0] = 0u | (4095u << 16); }
    __syncthreads();

    // ---- chunk maxima (order-independent -> lane-rotated conflict-free scan)
    if (tid < NCH) {
        int base = tid << 5;
        u64 m0 = 0, m1 = 0, m2 = 0, m3 = 0;
        #pragma unroll
        for (int i = 0; i < 32; i += 4) {
            m0 = umax64(m0, Af[base + ((i + 0 + lane) & 31)]);
            m1 = umax64(m1, Af[base + ((i + 1 + lane) & 31)]);
            m2 = umax64(m2, Af[base + ((i + 2 + lane) & 31)]);
            m3 = umax64(m3, Af[base + ((i + 3 + lane) & 31)]);
        }
        ST[0][tid] = umax64(umax64(m0, m1), umax64(m2, m3));
    }
    __syncthreads();

    // ---- sparse table over chunks
    #pragma unroll
    for (int j = 1; j < STL; j++) {
        if (tid < NCH) {
            int w = 1 << (j - 1);
            u64 a = ST[j - 1][tid];
            u64 b = (tid + w < NCH) ? ST[j - 1][tid + w] : 0ull;
            ST[j][tid] = umax64(a, b);
        }
        __syncthreads();
    }

    // ---- interval-tree worklist: each interval's max is kept; split around [p-d, p+d]
    u32* cur = listA; u32* nxt = listB;
    int* pN = &nA;    int* pM = &nB;
    for (;;) {
        int n = *pN;
        if (n == 0) break;
        if (tid < n) {
            u32 iv = cur[tid];
            int l = (int)(iv & 0xFFFFu), r = (int)(iv >> 16);
            int cl = l >> 5, cr = r >> 5;
            u64 m = 0;
            if (cl == cr) {
                for (int q = l; q <= r; q++) m = umax64(m, Af[q]);
            } else {
                int le = (cl << 5) | 31;
                for (int q = l; q <= le; q++) m = umax64(m, Af[q]);     // left partial
                int rs = cr << 5;
                for (int q = rs; q <= r; q++) m = umax64(m, Af[q]);     // right partial
                int a = cl + 1, b = cr - 1;
                if (a <= b) {                                            // full middle chunks: O(1) RMQ
                    int k = 31 - __clz(b - a + 1);
                    m = umax64(m, umax64(ST[k][a], ST[k][b - (1 << k) + 1]));
                }
            }
            if (m) {
                int p = L_LEN - (int)(m & 0x1FFFull);
                keep[p] = 1;
                int lc = p - DRAD - 1, rc = p + DRAD + 1;
                if (lc >= l) { int i2 = atomicAdd(pM, 1); nxt[i2] = (u32)l | ((u32)lc << 16); }
                if (rc <= r) { int i2 = atomicAdd(pM, 1); nxt[i2] = (u32)rc | ((u32)r << 16); }
            }
        }
        __syncthreads();                 // children + keep flags published
        u32* t = cur; cur = nxt; nxt = t;
        int* tp = pN; pN = pM; pM = tp;
        if (tid == 0) *pM = 0;
        __syncthreads();                 // count reset visible before next appends
    }

    // ---- output
    float* orow = out + (size_t)blockIdx.x * L_LEN;
    #pragma unroll
    for (int k = 0; k < PER; k++) {
        int p = tid + k * NTHR;
        orow[p] = keep[p] ? xv[k] : 0.0f;
    }
}

extern "C" void kernel_launch(void* const* d_in, const int* in_sizes, int n_in,
                              void* d_out, int out_size)
{
    const float* x = (const float*)d_in[0];
    float* out = (float*)d_out;
    // d_in[1] is minimum_extrema_distance = 32 (compile-time constant DRAD)
    int nrows = out_size / L_LEN;   // 128
    extrema_nms_kernel<<<nrows, NTHR>>>(x, out);
}

// round 4
// speedup vs baseline: 1.3957x; 1.2440x over previous
#include <cuda_runtime.h>

#define L_LEN   4096
#define DRAD    32                 // minimum_extrema_distance (fixed for this problem)
#define NTHR    256
#define PER     (L_LEN / NTHR)     // 16
#define NCH     (L_LEN / 32)       // 128 chunks of 32
#define STL     7                  // sparse-table levels over 128 chunks
#define WCAP    192                // per-round worklist capacity (<= ~64 used)

typedef unsigned long long u64;
typedef unsigned int u32;

// dynamic smem layout (bytes):
//   Af   [4096] u64   @ 0        32KB   raw keys (for short in-chunk scans)
//   pre  [4096] u64   @ 32768    32KB   within-chunk inclusive prefix max   (aliased as xs float[4096] during build)
//   suf  [4096] u64   @ 65536    32KB   within-chunk inclusive suffix max
//   ST [7][128] u64   @ 98304     7KB   sparse table over chunk maxima
//   keep [4096] u8    @ 105472    4KB
#define OFF_AF   0
#define OFF_PRE  32768
#define OFF_SUF  65536
#define OFF_ST   98304
#define OFF_KEEP 105472
#define SMEM_BYTES (OFF_KEEP + L_LEN)

__device__ __forceinline__ u64 umax64(u64 a, u64 b) { return a > b ? a : b; }

__global__ void __launch_bounds__(NTHR, 1)
extrema_nms_kernel(const float* __restrict__ x, float* __restrict__ out)
{
    extern __shared__ unsigned char sraw[];
    u64* Af  = (u64*)(sraw + OFF_AF);
    u64* pre = (u64*)(sraw + OFF_PRE);
    u64* suf = (u64*)(sraw + OFF_SUF);
    u64 (*ST)[NCH] = (u64 (*)[NCH])(sraw + OFF_ST);
    unsigned char* keep = (unsigned char*)(sraw + OFF_KEEP);
    float* xs = (float*)(sraw + OFF_PRE);        // alias: dead before pre is written

    __shared__ u32 listA[WCAP], listB[WCAP];
    __shared__ int nA, nB;

    const int tid  = threadIdx.x;
    const int lane = tid & 31;
    const int wid  = tid >> 5;
    const float* xr = x + (size_t)blockIdx.x * L_LEN;

    // ---- stage x into smem (coalesced float4)
    {
        const float4* xv4 = (const float4*)xr;
        float4* xs4 = (float4*)xs;
        #pragma unroll
        for (int k = 0; k < PER / 4; k++) xs4[tid + k * NTHR] = xv4[tid + k * NTHR];
    }
    if (tid == 0) { nA = 1; nB = 0; listA[0] = 0u | (4095u << 16); }
    __syncthreads();

    // ---- keys: key = (fbits(|x|) << 13) | (L - p): desc |x|, ties -> lower p; unique, nonzero iff extremum
    float xv[PER];
    #pragma unroll
    for (int k = 0; k < PER; k++) {
        int p = tid + k * NTHR;
        float xi = xs[p];
        xv[k] = xi;
        keep[p] = 0;
        // reference pad semantics: dx padded right with 0 (>0 false), left with 0 (<=0 true)
        bool dxr = (p < L_LEN - 1) ? (xs[p + 1] > xi) : false;
        bool dxl = (p > 0)         ? (xi <= xs[p - 1]) : true;
        bool ispos = (xi > 0.0f);
        bool isext = (dxr && dxl && !ispos) || (!dxr && !dxl && ispos);
        u64 key = 0ull;
        if (isext) {
            u32 fb = __float_as_uint(fabsf(xi));
            key = (((u64)fb) << 13) | (u64)(L_LEN - p);
        }
        Af[p] = key;
    }
    __syncthreads();   // Af complete; xs (aliased by pre) is dead from here

    // ---- per-chunk prefix/suffix max via warp shuffles (chunk == warp == 32)
    for (int c = wid; c < NCH; c += NTHR / 32) {
        int base = c << 5;
        u64 v = Af[base + lane];
        u64 pm = v, sm = v;
        #pragma unroll
        for (int s = 1; s < 32; s <<= 1) {
            u64 tu = __shfl_up_sync(0xFFFFFFFFu, pm, s);
            if (lane >= s) pm = umax64(pm, tu);
            u64 td = __shfl_down_sync(0xFFFFFFFFu, sm, s);
            if (lane + s < 32) sm = umax64(sm, td);
        }
        pre[base + lane] = pm;
        suf[base + lane] = sm;
        if (lane == 0) ST[0][c] = sm;    // chunk max
    }
    __syncthreads();

    // ---- sparse table over chunk maxima
    #pragma unroll
    for (int j = 1; j < STL; j++) {
        if (tid < NCH) {
            int w = 1 << (j - 1);
            u64 a = ST[j - 1][tid];
            u64 b = (tid + w < NCH) ? ST[j - 1][tid + w] : 0ull;
            ST[j][tid] = umax64(a, b);
        }
        __syncthreads();
    }

    // ---- parallel DFS over the static greedy interval tree.
    // Keep the interval max; children are [l, p-33] and [p+33, r]. A thread continues
    // into one child locally (collapses chains) and pushes the sibling for the next round.
    u32* cur = listA; u32* nxt = listB;
    int* pN = &nA;    int* pM = &nB;
    int safety = 0;
    for (;;) {
        int n = *pN;
        if (n == 0 || ++safety > 64) break;
        if (tid < n) {
            u32 iv = cur[tid];
            int l = (int)(iv & 0xFFFFu), r = (int)(iv >> 16);
            for (;;) {
                int cl = l >> 5, cr = r >> 5;
                u64 m;
                if (cl == cr) {                      // short in-chunk range: serial scan (<=32)
                    m = Af[l];
                    for (int q = l + 1; q <= r; q++) m = umax64(m, Af[q]);
                } else {
                    m = umax64(suf[l], pre[r]);      // O(1) boundary pieces
                    int a = cl + 1, b = cr - 1;
                    if (a <= b) {                    // full middle chunks: O(1) RMQ
                        int k = 31 - __clz(b - a + 1);
                        m = umax64(m, umax64(ST[k][a], ST[k][b - (1 << k) + 1]));
                    }
                }
                if (!m) break;                       // no extremum in interval
                int p = L_LEN - (int)(m & 0x1FFFull);
                keep[p] = 1;
                int lc = p - (DRAD + 1), rc = p + (DRAD + 1);
                bool hasL = (lc >= l), hasR = (rc <= r);
                if (hasL & hasR) {
                    int i2 = atomicAdd(pM, 1);       // push right sibling, continue left
                    nxt[i2] = (u32)rc | ((u32)r << 16);
                    r = lc;
                } else if (hasL) {
                    r = lc;
                } else if (hasR) {
                    l = rc;
                } else break;
            }
        }
        __syncthreads();                 // children + keep flags published
        u32* t = cur; cur = nxt; nxt = t;
        int* tp = pN; pN = pM; pM = tp;
        if (tid == 0) *pM = 0;           // reset the now-old counter
        __syncthreads();
    }

    // ---- output
    float* orow = out + (size_t)blockIdx.x * L_LEN;
    #pragma unroll
    for (int k = 0; k < PER; k++) {
        int p = tid + k * NTHR;
        orow[p] = keep[p] ? xv[k] : 0.0f;
    }
}

extern "C" void kernel_launch(void* const* d_in, const int* in_sizes, int n_in,
                              void* d_out, int out_size)
{
    const float* x = (const float*)d_in[0];
    float* out = (float*)d_out;
    // d_in[1] is minimum_extrema_distance = 32 (compile-time constant DRAD)

    cudaFuncSetAttribute(extrema_nms_kernel,
                         cudaFuncAttributeMaxDynamicSharedMemorySize, SMEM_BYTES);

    int nrows = out_size / L_LEN;   // 128
    extrema_nms_kernel<<<nrows, NTHR, SMEM_BYTES>>>(x, out);
}